// round 1
// baseline (speedup 1.0000x reference)
#include <cuda_runtime.h>

#define N_NODES 10000
#define N_EDGES 320000
#define NVEC 17
#define CHUNK 256

// Probe-vector storage: 17 vectors of length N (operator strings over {S0^T, S1^T} applied to e_0)
__device__ float g_R[NVEC][N_NODES];
__device__ float g_D[NVEC][4][64];   // D[v][b][f] = sum_n R[v][n] * x[b][n][f]
__device__ float g_sig[5];           // column sums of the 5 layer-2 probe vectors
__device__ float g_T[5][4][128];     // intermediate (post-W1) vectors per layer-2 s-string

// VEC_ID[s_idx][p_idx] -> vector id for string s++p
// s/p index order: {eps, "0", "00", "1", "11"}
__constant__ int c_VEC_ID[5][5] = {
    {0, 1, 3, 2, 6},
    {1, 3, 7, 4, 9},
    {3, 7, 13, 8, 14},
    {2, 5, 10, 6, 12},
    {6, 11, 15, 12, 16}};

struct Jobs {
    int parent[6];
    int child[6];
    int gso[6];
    int n;
};

__global__ void zero_kernel() {
    int i = blockIdx.x * blockDim.x + threadIdx.x;
    float* R = &g_R[0][0];
    if (i < NVEC * N_NODES) R[i] = 0.0f;
    float* D = &g_D[0][0][0];
    if (i < NVEC * 4 * 64) D[i] = 0.0f;
    if (i == 0) {
        g_R[0][0] = 1.0f;   // a = e_0  (same thread wrote the 0 above; program order holds)
        g_sig[0] = 1.0f;
    }
}

// One level of the probe tree: for each job, R[child] += S_g^T R[parent]
// (S^T q)[col_j] += val_j * q[row_j]; skip exact zeros (early levels are very sparse).
__global__ void lvl_kernel(const int* __restrict__ eidx,
                           const float* __restrict__ evals, Jobs jobs) {
    int job = blockIdx.y;
    int g = jobs.gso[job];
    const int* rows = eidx + (size_t)g * 2 * N_EDGES;
    const int* cols = rows + N_EDGES;
    const float* vals = evals + (size_t)g * N_EDGES;
    const float* __restrict__ Rp = g_R[jobs.parent[job]];
    float* Rc = g_R[jobs.child[job]];
    int stride = gridDim.x * blockDim.x;
    for (int j = blockIdx.x * blockDim.x + threadIdx.x; j < N_EDGES; j += stride) {
        float p = Rp[rows[j]];
        if (p != 0.0f) {
            atomicAdd(&Rc[cols[j]], vals[j] * p);
        }
    }
}

// D[v][b][f] = sum_n R[v][n] * x[b][n][f]  — batched as 4 GEMMs [17,N]x[N,64]
__global__ void dot_kernel(const float* __restrict__ x) {
    __shared__ float Rs[NVEC * CHUNK];  // 17*256*4 = 17.4 KB
    int b = blockIdx.y;
    int chunk0 = blockIdx.x * CHUNK;
    int tid = threadIdx.x;  // 256 threads

    for (int idx = tid; idx < NVEC * CHUNK; idx += 256) {
        int v = idx / CHUNK, n = idx - v * CHUNK;
        int gn = chunk0 + n;
        Rs[idx] = (gn < N_NODES) ? g_R[v][gn] : 0.0f;
    }
    __syncthreads();

    int f = tid & 63, sub = tid >> 6;
    float acc[NVEC];
#pragma unroll
    for (int v = 0; v < NVEC; v++) acc[v] = 0.0f;

    const float* xb = x + (size_t)b * N_NODES * 64;
    for (int i = 0; i < CHUNK / 4; i++) {
        int nn = i * 4 + sub;
        int gn = chunk0 + nn;
        float xv = (gn < N_NODES) ? __ldg(xb + (size_t)gn * 64 + f) : 0.0f;
#pragma unroll
        for (int v = 0; v < NVEC; v++) acc[v] += Rs[v * CHUNK + nn] * xv;  // LDS broadcast
    }
    __syncthreads();

    // cross-sub reduce in smem, then one atomic per (v,f) per block
#pragma unroll
    for (int v = 0; v < NVEC; v++) Rs[v * 256 + tid] = acc[v];
    __syncthreads();
    if (sub == 0) {
#pragma unroll
        for (int v = 0; v < NVEC; v++) {
            float s = Rs[v * 256 + f] + Rs[v * 256 + 64 + f] +
                      Rs[v * 256 + 128 + f] + Rs[v * 256 + 192 + f];
            atomicAdd(&g_D[v][b][f], s);
        }
    }
}

// sigma[si] = 1^T q_si for si=1..4 (vectors "0","00","1","11" -> ids 1,3,2,6)
__global__ void sigma_kernel() {
    const int vids[4] = {1, 3, 2, 6};
    int vid = vids[blockIdx.x];
    __shared__ float sh[256];
    float s = 0.0f;
    for (int n = threadIdx.x; n < N_NODES; n += 256) s += g_R[vid][n];
    sh[threadIdx.x] = s;
    __syncthreads();
    for (int off = 128; off; off >>= 1) {
        if (threadIdx.x < off) sh[threadIdx.x] += sh[threadIdx.x + off];
        __syncthreads();
    }
    if (threadIdx.x == 0) g_sig[blockIdx.x + 1] = sh[0];
}

// T[si][b][g1] = sum_{(e,k)} D[VEC_ID[si][pi(e,k)]][b][:] . W1[e,k][:,g1] + sig[si]*b1[g1]
__global__ void t_kernel(const float* __restrict__ W1, const float* __restrict__ b1) {
    int si = blockIdx.x, b = blockIdx.y, gcol = threadIdx.x;  // 128 threads
    float t = g_sig[si] * b1[gcol];
#pragma unroll
    for (int pc = 0; pc < 6; pc++) {
        int e = pc / 3, k = pc % 3;
        int pi = (k == 0) ? 0 : (e * 2 + k);
        int vid = c_VEC_ID[si][pi];
        const float* Wp = W1 + (size_t)pc * 64 * 128;
        const float* Dp = g_D[vid][b];
#pragma unroll
        for (int f = 0; f < 64; f++) t += Dp[f] * Wp[f * 128 + gcol];
    }
    g_T[si][b][gcol] = t;
}

// out[b][g2] = sum_{(e',k')} T[ss(e',k')][b][:] . W2[e',k'][:,g2] + b2[g2]
__global__ void out_kernel(const float* __restrict__ W2, const float* __restrict__ b2,
                           float* __restrict__ out) {
    int b = blockIdx.x, gcol = threadIdx.x;  // 128 threads
    float t = b2[gcol];
#pragma unroll
    for (int pc = 0; pc < 6; pc++) {
        int e = pc / 3, k = pc % 3;
        int si = (k == 0) ? 0 : (e * 2 + k);
        const float* Wp = W2 + (size_t)pc * 128 * 128;
        const float* Tp = g_T[si][b];
#pragma unroll
        for (int f = 0; f < 128; f++) t += Tp[f] * Wp[f * 128 + gcol];
    }
    out[b * 128 + gcol] = t;
}

static void set_job(Jobs& J, int i, int p, int c, int g) {
    J.parent[i] = p; J.child[i] = c; J.gso[i] = g;
}

extern "C" void kernel_launch(void* const* d_in, const int* in_sizes, int n_in,
                              void* d_out, int out_size) {
    // Size-based remap (robust to metadata ordering; the two 128-vectors keep
    // their relative order b1 then b2 in both dict and alphabetical orders).
    const float* x = nullptr;
    const int* eidx = nullptr;
    const float* evals = nullptr;
    const float *W1 = nullptr, *b1 = nullptr, *W2 = nullptr, *b2 = nullptr;
    for (int i = 0; i < n_in; i++) {
        switch (in_sizes[i]) {
            case 2560000: x = (const float*)d_in[i]; break;        // [4,10000,64]
            case 1280000: eidx = (const int*)d_in[i]; break;       // [2,2,320000]
            case 640000:  evals = (const float*)d_in[i]; break;    // [2,320000]
            case 49152:   W1 = (const float*)d_in[i]; break;       // [2,3,64,128]
            case 98304:   W2 = (const float*)d_in[i]; break;       // [2,3,128,128]
            case 128:
                if (!b1) b1 = (const float*)d_in[i];
                else b2 = (const float*)d_in[i];
                break;
        }
    }
    float* out = (float*)d_out;

    zero_kernel<<<(NVEC * N_NODES + 255) / 256, 256>>>();

    Jobs j1{}; j1.n = 2;
    set_job(j1, 0, 0, 1, 0);   // "0"  = S0^T a
    set_job(j1, 1, 0, 2, 1);   // "1"  = S1^T a
    lvl_kernel<<<dim3(320, j1.n), 256>>>(eidx, evals, j1);

    Jobs j2{}; j2.n = 4;
    set_job(j2, 0, 1, 3, 0);   // "00"
    set_job(j2, 1, 1, 4, 1);   // "01"
    set_job(j2, 2, 2, 5, 0);   // "10"
    set_job(j2, 3, 2, 6, 1);   // "11"
    lvl_kernel<<<dim3(320, j2.n), 256>>>(eidx, evals, j2);

    Jobs j3{}; j3.n = 6;
    set_job(j3, 0, 3, 7, 0);   // "000"
    set_job(j3, 1, 3, 8, 1);   // "001"
    set_job(j3, 2, 4, 9, 1);   // "011"
    set_job(j3, 3, 5, 10, 0);  // "100"
    set_job(j3, 4, 6, 11, 0);  // "110"
    set_job(j3, 5, 6, 12, 1);  // "111"
    lvl_kernel<<<dim3(320, j3.n), 256>>>(eidx, evals, j3);

    Jobs j4{}; j4.n = 4;
    set_job(j4, 0, 7, 13, 0);   // "0000"
    set_job(j4, 1, 8, 14, 1);   // "0011"
    set_job(j4, 2, 11, 15, 0);  // "1100"
    set_job(j4, 3, 12, 16, 1);  // "1111"
    lvl_kernel<<<dim3(320, j4.n), 256>>>(eidx, evals, j4);

    dot_kernel<<<dim3((N_NODES + CHUNK - 1) / CHUNK, 4), 256>>>(x);
    sigma_kernel<<<4, 256>>>();
    t_kernel<<<dim3(5, 4), 128>>>(W1, b1);
    out_kernel<<<4, 128>>>(W2, b2, out);
}

// round 2
// speedup vs baseline: 1.1170x; 1.1170x over previous
#include <cuda_runtime.h>

#define N_NODES 10000
#define N_EDGES 320000
#define NVEC 17
#define CHUNK 256

__device__ float g_R[NVEC][N_NODES];
__device__ float g_D[NVEC][4][64];   // D[v][b][f] = sum_n R[v][n] * x[b][n][f]
__device__ float g_sig[5];           // column sums of the 5 layer-2 probe vectors
__device__ float g_T[5][4][128];     // intermediate (post-W1) vectors

// VEC_ID[s_idx][p_idx] -> vector id for string s++p; order {eps,"0","00","1","11"}
__constant__ int c_VEC_ID[5][5] = {
    {0, 1, 3, 2, 6},
    {1, 3, 7, 4, 9},
    {3, 7, 13, 8, 14},
    {2, 5, 10, 6, 12},
    {6, 11, 15, 12, 16}};

struct Lvl { int p[2][3]; int c[2][3]; };

__global__ void zero_kernel() {
    int i = blockIdx.x * blockDim.x + threadIdx.x;
    float* R = &g_R[0][0];
    if (i < NVEC * N_NODES) R[i] = 0.0f;
    float* D = &g_D[0][0][0];
    if (i < NVEC * 4 * 64) D[i] = 0.0f;
    if (i < 5) g_sig[i] = (i == 0) ? 1.0f : 0.0f;
    if (i == 0) g_R[0][0] = 1.0f;  // e_0 (same thread wrote the 0; program order)
}

// Fused level scan: for each GSO (blockIdx.y), apply S_g^T to NJ parent vectors
// in ONE pass over the edge stream, int4/float4 vectorized (4 edges / thread-iter).
template <int NJ>
__global__ void lvl_kernel(const int* __restrict__ eidx,
                           const float* __restrict__ evals, Lvl L) {
    int g = blockIdx.y;
    const int4* rows4 = (const int4*)(eidx + (size_t)g * 2 * N_EDGES);
    const int4* cols4 = (const int4*)(eidx + (size_t)g * 2 * N_EDGES + N_EDGES);
    const float4* vals4 = (const float4*)(evals + (size_t)g * N_EDGES);

    const float* Rp[NJ];
    float* Rc[NJ];
#pragma unroll
    for (int t = 0; t < NJ; t++) {
        Rp[t] = g_R[L.p[g][t]];
        Rc[t] = g_R[L.c[g][t]];
    }

    int stride = gridDim.x * blockDim.x;
    for (int j = blockIdx.x * blockDim.x + threadIdx.x; j < N_EDGES / 4; j += stride) {
        int4 r = rows4[j];
        float p[NJ][4];
        bool any = false;
#pragma unroll
        for (int t = 0; t < NJ; t++) {
            p[t][0] = Rp[t][r.x]; p[t][1] = Rp[t][r.y];
            p[t][2] = Rp[t][r.z]; p[t][3] = Rp[t][r.w];
            any |= (p[t][0] != 0.0f) | (p[t][1] != 0.0f) |
                   (p[t][2] != 0.0f) | (p[t][3] != 0.0f);
        }
        if (!any) continue;
        int4 c = cols4[j];
        float4 v = vals4[j];
#pragma unroll
        for (int t = 0; t < NJ; t++) {
            if (p[t][0] != 0.0f) atomicAdd(&Rc[t][c.x], v.x * p[t][0]);
            if (p[t][1] != 0.0f) atomicAdd(&Rc[t][c.y], v.y * p[t][1]);
            if (p[t][2] != 0.0f) atomicAdd(&Rc[t][c.z], v.z * p[t][2]);
            if (p[t][3] != 0.0f) atomicAdd(&Rc[t][c.w], v.w * p[t][3]);
        }
    }
}

// D[v][b][f] = sum_n R[v][n] * x[b][n][f]; also folds the sigma column-sums.
__global__ void dot_kernel(const float* __restrict__ x) {
    __shared__ float Rs[NVEC * CHUNK];  // 17 KB
    int b = blockIdx.y;
    int chunk0 = blockIdx.x * CHUNK;
    int tid = threadIdx.x;  // 256

    for (int idx = tid; idx < NVEC * CHUNK; idx += 256) {
        int v = idx / CHUNK, n = idx - v * CHUNK;
        int gn = chunk0 + n;
        Rs[idx] = (gn < N_NODES) ? g_R[v][gn] : 0.0f;
    }
    __syncthreads();

    // sigma (only b==0 grid row): vectors {"0","00","1","11"} = ids {1,3,2,6}
    if (b == 0 && tid < 128) {
        const int vids[4] = {1, 3, 2, 6};
        int vi = tid >> 5, lane = tid & 31;
        float s = 0.0f;
        for (int n = lane; n < CHUNK; n += 32) s += Rs[vids[vi] * CHUNK + n];
#pragma unroll
        for (int off = 16; off; off >>= 1) s += __shfl_down_sync(0xffffffffu, s, off);
        if (lane == 0) atomicAdd(&g_sig[vi + 1], s);
    }

    int f = tid & 63, sub = tid >> 6;
    float acc[NVEC];
#pragma unroll
    for (int v = 0; v < NVEC; v++) acc[v] = 0.0f;

    const float* xb = x + (size_t)b * N_NODES * 64;
    for (int i = 0; i < CHUNK / 4; i++) {
        int nn = i * 4 + sub;
        int gn = chunk0 + nn;
        float xv = (gn < N_NODES) ? __ldg(xb + (size_t)gn * 64 + f) : 0.0f;
#pragma unroll
        for (int v = 0; v < NVEC; v++) acc[v] += Rs[v * CHUNK + nn] * xv;
    }
    __syncthreads();

#pragma unroll
    for (int v = 0; v < NVEC; v++) Rs[v * 256 + tid] = acc[v];
    __syncthreads();
    if (sub == 0) {
#pragma unroll
        for (int v = 0; v < NVEC; v++) {
            float s = Rs[v * 256 + f] + Rs[v * 256 + 64 + f] +
                      Rs[v * 256 + 128 + f] + Rs[v * 256 + 192 + f];
            atomicAdd(&g_D[v][b][f], s);
        }
    }
}

// T[si][b][:] = sum_{(e,k)} D[vid][b][:] W1[e,k] + sig[si]*b1
// 128 thr: lane handles 4 gcols (float4), 4 subs split the f-sum.
__global__ void t_kernel(const float* __restrict__ W1, const float* __restrict__ b1) {
    __shared__ float4 red[128];
    int si = blockIdx.x, b = blockIdx.y;
    int lane = threadIdx.x & 31, sub = threadIdx.x >> 5;
    float4 acc = {0, 0, 0, 0};
    if (sub == 0) {
        float sg = g_sig[si];
        const float4* b14 = (const float4*)b1;
        float4 bb = b14[lane];
        acc.x = sg * bb.x; acc.y = sg * bb.y; acc.z = sg * bb.z; acc.w = sg * bb.w;
    }
#pragma unroll
    for (int pc = 0; pc < 6; pc++) {
        int e = pc / 3, k = pc % 3;
        int pi = (k == 0) ? 0 : (e * 2 + k);
        int vid = c_VEC_ID[si][pi];
        const float* Dp = g_D[vid][b];
        const float* Wp = W1 + (size_t)pc * 64 * 128;
#pragma unroll
        for (int fi = 0; fi < 16; fi++) {
            int f = fi * 4 + sub;
            float d = Dp[f];
            float4 w = __ldg((const float4*)(Wp + (size_t)f * 128) + lane);
            acc.x += d * w.x; acc.y += d * w.y; acc.z += d * w.z; acc.w += d * w.w;
        }
    }
    red[threadIdx.x] = acc;
    __syncthreads();
    if (sub == 0) {
        float4 a = red[lane], b1_ = red[32 + lane], c = red[64 + lane], d = red[96 + lane];
        float4 o;
        o.x = a.x + b1_.x + c.x + d.x;
        o.y = a.y + b1_.y + c.y + d.y;
        o.z = a.z + b1_.z + c.z + d.z;
        o.w = a.w + b1_.w + c.w + d.w;
        ((float4*)g_T[si][b])[lane] = o;
    }
}

// out[b][:] = sum_{(e',k')} T[ss][b][:] W2[e',k'] + b2
__global__ void out_kernel(const float* __restrict__ W2, const float* __restrict__ b2,
                           float* __restrict__ out) {
    __shared__ float4 red[128];
    int b = blockIdx.x;
    int lane = threadIdx.x & 31, sub = threadIdx.x >> 5;
    float4 acc = {0, 0, 0, 0};
    if (sub == 0) acc = ((const float4*)b2)[lane];
#pragma unroll
    for (int pc = 0; pc < 6; pc++) {
        int e = pc / 3, k = pc % 3;
        int si = (k == 0) ? 0 : (e * 2 + k);
        const float* Tp = g_T[si][b];
        const float* Wp = W2 + (size_t)pc * 128 * 128;
#pragma unroll
        for (int fi = 0; fi < 32; fi++) {
            int f = fi * 4 + sub;
            float t = Tp[f];
            float4 w = __ldg((const float4*)(Wp + (size_t)f * 128) + lane);
            acc.x += t * w.x; acc.y += t * w.y; acc.z += t * w.z; acc.w += t * w.w;
        }
    }
    red[threadIdx.x] = acc;
    __syncthreads();
    if (sub == 0) {
        float4 a = red[lane], bb = red[32 + lane], c = red[64 + lane], d = red[96 + lane];
        float4 o;
        o.x = a.x + bb.x + c.x + d.x;
        o.y = a.y + bb.y + c.y + d.y;
        o.z = a.z + bb.z + c.z + d.z;
        o.w = a.w + bb.w + c.w + d.w;
        ((float4*)(out + (size_t)b * 128))[lane] = o;
    }
}

extern "C" void kernel_launch(void* const* d_in, const int* in_sizes, int n_in,
                              void* d_out, int out_size) {
    const float* x = nullptr;
    const int* eidx = nullptr;
    const float* evals = nullptr;
    const float *W1 = nullptr, *b1 = nullptr, *W2 = nullptr, *b2 = nullptr;
    for (int i = 0; i < n_in; i++) {
        switch (in_sizes[i]) {
            case 2560000: x = (const float*)d_in[i]; break;
            case 1280000: eidx = (const int*)d_in[i]; break;
            case 640000:  evals = (const float*)d_in[i]; break;
            case 49152:   W1 = (const float*)d_in[i]; break;
            case 98304:   W2 = (const float*)d_in[i]; break;
            case 128:
                if (!b1) b1 = (const float*)d_in[i];
                else b2 = (const float*)d_in[i];
                break;
        }
    }
    float* out = (float*)d_out;

    zero_kernel<<<(NVEC * N_NODES + 255) / 256, 256>>>();

    const int BLK = 313;  // ceil(80000/256)

    Lvl L1 = {{{0}, {0}}, {{1}, {2}}};
    lvl_kernel<1><<<dim3(BLK, 2), 256>>>(eidx, evals, L1);

    Lvl L2 = {{{1, 2}, {1, 2}}, {{3, 5}, {4, 6}}};
    lvl_kernel<2><<<dim3(BLK, 2), 256>>>(eidx, evals, L2);

    Lvl L3 = {{{3, 5, 6}, {3, 4, 6}}, {{7, 10, 11}, {8, 9, 12}}};
    lvl_kernel<3><<<dim3(BLK, 2), 256>>>(eidx, evals, L3);

    Lvl L4 = {{{7, 11}, {8, 12}}, {{13, 15}, {14, 16}}};
    lvl_kernel<2><<<dim3(BLK, 2), 256>>>(eidx, evals, L4);

    dot_kernel<<<dim3((N_NODES + CHUNK - 1) / CHUNK, 4), 256>>>(x);
    t_kernel<<<dim3(5, 4), 128>>>(W1, b1);
    out_kernel<<<4, 128>>>(W2, b2, out);
}

// round 3
// speedup vs baseline: 1.2606x; 1.1286x over previous
#include <cuda_runtime.h>

#define N_NODES 10000
#define N_EDGES 320000
#define CHUNK 256

// Packed probe-vector storage (one struct-of-slots array per tree level).
__device__ float2 g_CL1[N_NODES];   // {R1, R2}
__device__ float4 g_CL2[N_NODES];   // {R3, R5, R4, R6}
__device__ float4 g_CL3a[N_NODES];  // {R7, R10, R11, pad}   (GSO0 children)
__device__ float4 g_CL3b[N_NODES];  // {R8, R9, R12, pad}    (GSO1 children)
__device__ float4 g_CL4[N_NODES];   // {R13, R15, R14, R16}
__device__ float g_D[17][4][64];    // D[v][b][f] = sum_n R[v][n] x[b][n][f]
__device__ float g_sig[5];          // column sums (sig[0] unused; =1 analytically)

// VEC_ID[s_idx][p_idx] -> vector id for string s++p; order {eps,"0","00","1","11"}
__constant__ int c_VEC_ID[5][5] = {
    {0, 1, 3, 2, 6},
    {1, 3, 7, 4, 9},
    {3, 7, 13, 8, 14},
    {2, 5, 10, 6, 12},
    {6, 11, 15, 12, 16}};

// smem slot s -> original vid
__constant__ int c_SVID[16] = {1, 2, 3, 5, 4, 6, 7, 10, 11, 8, 9, 12, 13, 15, 14, 16};

__device__ __forceinline__ void red2(float* p, float a, float b) {
    asm volatile("red.global.add.v2.f32 [%0], {%1,%2};" :: "l"(p), "f"(a), "f"(b) : "memory");
}
__device__ __forceinline__ void red4(float* p, float a, float b, float c, float d) {
    asm volatile("red.global.add.v4.f32 [%0], {%1,%2,%3,%4};"
                 :: "l"(p), "f"(a), "f"(b), "f"(c), "f"(d) : "memory");
}

__global__ void zero_kernel() {
    int i = blockIdx.x * blockDim.x + threadIdx.x;
    // 18 floats per node of packed storage
    if (i < N_NODES) {
        g_CL1[i] = make_float2(0.f, 0.f);
        float4 z = make_float4(0.f, 0.f, 0.f, 0.f);
        g_CL2[i] = z; g_CL3a[i] = z; g_CL3b[i] = z; g_CL4[i] = z;
    }
    float* D = &g_D[0][0][0];
    if (i < 17 * 4 * 64) D[i] = 0.0f;
    if (i < 5) g_sig[i] = 0.0f;
}

// Level 1: parent is e_0 (no gather): R1/R2[c] += v where row==0.
__global__ void lvl1_kernel(const int* __restrict__ eidx, const float* __restrict__ evals) {
    int g = blockIdx.y;
    const int4* rows4 = (const int4*)(eidx + (size_t)g * 2 * N_EDGES);
    const int4* cols4 = (const int4*)(eidx + (size_t)g * 2 * N_EDGES + N_EDGES);
    const float4* vals4 = (const float4*)(evals + (size_t)g * N_EDGES);
    int j = blockIdx.x * blockDim.x + threadIdx.x;
    if (j >= N_EDGES / 4) return;
    int4 r = rows4[j];
    if ((r.x | r.y | r.z | r.w) == 0 || r.x == 0 || r.y == 0 || r.z == 0 || r.w == 0) {
        int4 c = cols4[j];
        float4 v = vals4[j];
        float* base = (float*)g_CL1;
        if (r.x == 0) atomicAdd(base + c.x * 2 + g, v.x);
        if (r.y == 0) atomicAdd(base + c.y * 2 + g, v.y);
        if (r.z == 0) atomicAdd(base + c.z * 2 + g, v.z);
        if (r.w == 0) atomicAdd(base + c.w * 2 + g, v.w);
    }
}

// Level 2: gather float2 {R1,R2}; children v2-red into CL2 (GSO0 -> slots 0,1; GSO1 -> 2,3)
__global__ void lvl2_kernel(const int* __restrict__ eidx, const float* __restrict__ evals) {
    int g = blockIdx.y;
    const int4* rows4 = (const int4*)(eidx + (size_t)g * 2 * N_EDGES);
    const int4* cols4 = (const int4*)(eidx + (size_t)g * 2 * N_EDGES + N_EDGES);
    const float4* vals4 = (const float4*)(evals + (size_t)g * N_EDGES);
    int j = blockIdx.x * blockDim.x + threadIdx.x;
    if (j >= N_EDGES / 4) return;
    int4 r = rows4[j];
    float2 q0 = g_CL1[r.x], q1 = g_CL1[r.y], q2 = g_CL1[r.z], q3 = g_CL1[r.w];
    bool a0 = (q0.x != 0.f) | (q0.y != 0.f);
    bool a1 = (q1.x != 0.f) | (q1.y != 0.f);
    bool a2 = (q2.x != 0.f) | (q2.y != 0.f);
    bool a3 = (q3.x != 0.f) | (q3.y != 0.f);
    if (!(a0 | a1 | a2 | a3)) return;
    int4 c = cols4[j];
    float4 v = vals4[j];
    float* base = (float*)g_CL2 + 2 * g;
    if (a0) red2(base + c.x * 4, v.x * q0.x, v.x * q0.y);
    if (a1) red2(base + c.y * 4, v.y * q1.x, v.y * q1.y);
    if (a2) red2(base + c.z * 4, v.z * q2.x, v.z * q2.y);
    if (a3) red2(base + c.w * 4, v.w * q3.x, v.w * q3.y);
}

// Level 3: gather float4 CL2; GSO0 uses {R3,R5,R6}=slots{0,1,3} -> v4-red into CL3a;
// GSO1 uses {R3,R4,R6}=slots{0,2,3} -> CL3b.
__global__ void lvl3_kernel(const int* __restrict__ eidx, const float* __restrict__ evals) {
    int g = blockIdx.y;
    const int4* rows4 = (const int4*)(eidx + (size_t)g * 2 * N_EDGES);
    const int4* cols4 = (const int4*)(eidx + (size_t)g * 2 * N_EDGES + N_EDGES);
    const float4* vals4 = (const float4*)(evals + (size_t)g * N_EDGES);
    float4* dst = g ? g_CL3b : g_CL3a;
    int j = blockIdx.x * blockDim.x + threadIdx.x;
    if (j >= N_EDGES / 4) return;
    int4 r = rows4[j];
    float4 q[4] = {g_CL2[r.x], g_CL2[r.y], g_CL2[r.z], g_CL2[r.w]};
    float p[4][3];
    bool any[4];
#pragma unroll
    for (int i = 0; i < 4; i++) {
        p[i][0] = q[i].x;
        p[i][1] = g ? q[i].z : q[i].y;
        p[i][2] = q[i].w;
        any[i] = (p[i][0] != 0.f) | (p[i][1] != 0.f) | (p[i][2] != 0.f);
    }
    if (!(any[0] | any[1] | any[2] | any[3])) return;
    int4 c = cols4[j];
    float4 v = vals4[j];
    const int ci[4] = {c.x, c.y, c.z, c.w};
    const float vv[4] = {v.x, v.y, v.z, v.w};
#pragma unroll
    for (int i = 0; i < 4; i++)
        if (any[i])
            red4((float*)&dst[ci[i]], vv[i] * p[i][0], vv[i] * p[i][1], vv[i] * p[i][2], 0.f);
}

// Level 4: gather float4 CL3a/b; use slots {0,2}; v2-red into CL4 (GSO0 slots 0,1; GSO1 2,3)
__global__ void lvl4_kernel(const int* __restrict__ eidx, const float* __restrict__ evals) {
    int g = blockIdx.y;
    const int4* rows4 = (const int4*)(eidx + (size_t)g * 2 * N_EDGES);
    const int4* cols4 = (const int4*)(eidx + (size_t)g * 2 * N_EDGES + N_EDGES);
    const float4* vals4 = (const float4*)(evals + (size_t)g * N_EDGES);
    const float4* src = g ? g_CL3b : g_CL3a;
    int j = blockIdx.x * blockDim.x + threadIdx.x;
    if (j >= N_EDGES / 4) return;
    int4 r = rows4[j];
    float4 q0 = src[r.x], q1 = src[r.y], q2 = src[r.z], q3 = src[r.w];
    int4 c = cols4[j];
    float4 v = vals4[j];
    float* base = (float*)g_CL4 + 2 * g;
    if ((q0.x != 0.f) | (q0.z != 0.f)) red2(base + c.x * 4, v.x * q0.x, v.x * q0.z);
    if ((q1.x != 0.f) | (q1.z != 0.f)) red2(base + c.y * 4, v.y * q1.x, v.y * q1.z);
    if ((q2.x != 0.f) | (q2.z != 0.f)) red2(base + c.z * 4, v.z * q2.x, v.z * q2.z);
    if ((q3.x != 0.f) | (q3.z != 0.f)) red2(base + c.w * 4, v.w * q3.x, v.w * q3.z);
}

// D[v][b][f] = sum_n R[v][n] x[b][n][f] for v=1..16; sigma folded in.
__global__ void dot_kernel(const float* __restrict__ x) {
    __shared__ float Rs[16 * CHUNK];  // 16 KB
    int b = blockIdx.y;
    int chunk0 = blockIdx.x * CHUNK;
    int tid = threadIdx.x;  // 256

    {
        int gn = chunk0 + tid;
        float2 a = {0, 0};
        float4 c2 = {0, 0, 0, 0}, c3a = c2, c3b = c2, c4 = c2;
        if (gn < N_NODES) {
            a = g_CL1[gn]; c2 = g_CL2[gn]; c3a = g_CL3a[gn]; c3b = g_CL3b[gn]; c4 = g_CL4[gn];
        }
        Rs[0 * CHUNK + tid] = a.x;   Rs[1 * CHUNK + tid] = a.y;
        Rs[2 * CHUNK + tid] = c2.x;  Rs[3 * CHUNK + tid] = c2.y;
        Rs[4 * CHUNK + tid] = c2.z;  Rs[5 * CHUNK + tid] = c2.w;
        Rs[6 * CHUNK + tid] = c3a.x; Rs[7 * CHUNK + tid] = c3a.y;
        Rs[8 * CHUNK + tid] = c3a.z;
        Rs[9 * CHUNK + tid] = c3b.x; Rs[10 * CHUNK + tid] = c3b.y;
        Rs[11 * CHUNK + tid] = c3b.z;
        Rs[12 * CHUNK + tid] = c4.x; Rs[13 * CHUNK + tid] = c4.y;
        Rs[14 * CHUNK + tid] = c4.z; Rs[15 * CHUNK + tid] = c4.w;
    }
    __syncthreads();

    // sigma for vids {1,3,2,6} = smem slots {0,2,1,5} (b==0 row only)
    if (b == 0 && tid < 128) {
        const int slots[4] = {0, 2, 1, 5};
        int vi = tid >> 5, lane = tid & 31;
        float s = 0.0f;
        for (int n = lane; n < CHUNK; n += 32) s += Rs[slots[vi] * CHUNK + n];
#pragma unroll
        for (int off = 16; off; off >>= 1) s += __shfl_down_sync(0xffffffffu, s, off);
        if (lane == 0) atomicAdd(&g_sig[vi + 1], s);
    }

    int f = tid & 63, sub = tid >> 6;
    float acc[16];
#pragma unroll
    for (int v = 0; v < 16; v++) acc[v] = 0.0f;

    const float* xb = x + (size_t)b * N_NODES * 64;
    for (int i = 0; i < CHUNK / 4; i++) {
        int nn = i * 4 + sub;
        int gn = chunk0 + nn;
        float xv = (gn < N_NODES) ? __ldg(xb + (size_t)gn * 64 + f) : 0.0f;
#pragma unroll
        for (int v = 0; v < 16; v++) acc[v] += Rs[v * CHUNK + nn] * xv;
    }
    __syncthreads();

#pragma unroll
    for (int v = 0; v < 16; v++) Rs[v * 256 + tid] = acc[v];
    __syncthreads();
    if (sub == 0) {
#pragma unroll
        for (int v = 0; v < 16; v++) {
            float s = Rs[v * 256 + f] + Rs[v * 256 + 64 + f] +
                      Rs[v * 256 + 128 + f] + Rs[v * 256 + 192 + f];
            atomicAdd(&g_D[c_SVID[v]][b][f], s);
        }
    }
}

// Fused epilogue: per-batch block computes T[si] (5 strings) then the output row.
__global__ void tout_kernel(const float* __restrict__ x,
                            const float* __restrict__ W1, const float* __restrict__ b1,
                            const float* __restrict__ W2, const float* __restrict__ b2,
                            float* __restrict__ out) {
    __shared__ float4 red[128];
    __shared__ float Ts[5][128];
    int b = blockIdx.x;
    int lane = threadIdx.x & 31, sub = threadIdx.x >> 5;
    const float* xb0 = x + (size_t)b * N_NODES * 64;  // D[0][b][:] = x[b][0][:]

    for (int si = 0; si < 5; si++) {
        float4 acc = {0, 0, 0, 0};
        if (sub == 0) {
            float sg = (si == 0) ? 1.0f : g_sig[si];
            float4 bb = ((const float4*)b1)[lane];
            acc.x = sg * bb.x; acc.y = sg * bb.y; acc.z = sg * bb.z; acc.w = sg * bb.w;
        }
#pragma unroll
        for (int pc = 0; pc < 6; pc++) {
            int e = pc / 3, k = pc % 3;
            int pi = (k == 0) ? 0 : (e * 2 + k);
            int vid = c_VEC_ID[si][pi];
            const float* Dp = (vid == 0) ? xb0 : g_D[vid][b];
            const float* Wp = W1 + (size_t)pc * 64 * 128;
#pragma unroll
            for (int fi = 0; fi < 16; fi++) {
                int f = fi * 4 + sub;
                float d = __ldg(Dp + f);
                float4 w = __ldg((const float4*)(Wp + (size_t)f * 128) + lane);
                acc.x += d * w.x; acc.y += d * w.y; acc.z += d * w.z; acc.w += d * w.w;
            }
        }
        red[threadIdx.x] = acc;
        __syncthreads();
        if (sub == 0) {
            float4 a = red[lane], bb = red[32 + lane], c = red[64 + lane], d = red[96 + lane];
            float4 o;
            o.x = a.x + bb.x + c.x + d.x;
            o.y = a.y + bb.y + c.y + d.y;
            o.z = a.z + bb.z + c.z + d.z;
            o.w = a.w + bb.w + c.w + d.w;
            ((float4*)Ts[si])[lane] = o;
        }
        __syncthreads();
    }

    // out phase
    float4 acc = {0, 0, 0, 0};
    if (sub == 0) acc = ((const float4*)b2)[lane];
#pragma unroll
    for (int pc = 0; pc < 6; pc++) {
        int e = pc / 3, k = pc % 3;
        int si = (k == 0) ? 0 : (e * 2 + k);
        const float* Tp = Ts[si];
        const float* Wp = W2 + (size_t)pc * 128 * 128;
#pragma unroll
        for (int fi = 0; fi < 32; fi++) {
            int f = fi * 4 + sub;
            float t = Tp[f];
            float4 w = __ldg((const float4*)(Wp + (size_t)f * 128) + lane);
            acc.x += t * w.x; acc.y += t * w.y; acc.z += t * w.z; acc.w += t * w.w;
        }
    }
    red[threadIdx.x] = acc;
    __syncthreads();
    if (sub == 0) {
        float4 a = red[lane], bb = red[32 + lane], c = red[64 + lane], d = red[96 + lane];
        float4 o;
        o.x = a.x + bb.x + c.x + d.x;
        o.y = a.y + bb.y + c.y + d.y;
        o.z = a.z + bb.z + c.z + d.z;
        o.w = a.w + bb.w + c.w + d.w;
        ((float4*)(out + (size_t)b * 128))[lane] = o;
    }
}

extern "C" void kernel_launch(void* const* d_in, const int* in_sizes, int n_in,
                              void* d_out, int out_size) {
    const float* x = nullptr;
    const int* eidx = nullptr;
    const float* evals = nullptr;
    const float *W1 = nullptr, *b1 = nullptr, *W2 = nullptr, *b2 = nullptr;
    for (int i = 0; i < n_in; i++) {
        switch (in_sizes[i]) {
            case 2560000: x = (const float*)d_in[i]; break;
            case 1280000: eidx = (const int*)d_in[i]; break;
            case 640000:  evals = (const float*)d_in[i]; break;
            case 49152:   W1 = (const float*)d_in[i]; break;
            case 98304:   W2 = (const float*)d_in[i]; break;
            case 128:
                if (!b1) b1 = (const float*)d_in[i];
                else b2 = (const float*)d_in[i];
                break;
        }
    }
    float* out = (float*)d_out;

    zero_kernel<<<(N_NODES + 255) / 256, 256>>>();

    const int BLK = 313;  // ceil(80000/256)
    lvl1_kernel<<<dim3(BLK, 2), 256>>>(eidx, evals);
    lvl2_kernel<<<dim3(BLK, 2), 256>>>(eidx, evals);
    lvl3_kernel<<<dim3(BLK, 2), 256>>>(eidx, evals);
    lvl4_kernel<<<dim3(BLK, 2), 256>>>(eidx, evals);

    dot_kernel<<<dim3((N_NODES + CHUNK - 1) / CHUNK, 4), 256>>>(x);
    tout_kernel<<<4, 128>>>(x, W1, b1, W2, b2, out);
}

// round 4
// speedup vs baseline: 1.2970x; 1.0288x over previous
#include <cuda_runtime.h>

#define N_NODES 10000
#define N_EDGES 320000
#define QUADS (N_EDGES / 4)
#define NB 148
#define NT 1024
#define NTHR (NB * NT)
#define DCHUNK 128
#define NCHUNK ((N_NODES + DCHUNK - 1) / DCHUNK)  // 79

// Packed probe-vector storage (struct-of-slots per tree level).
__device__ float2 g_CL1[N_NODES];   // {R1, R2}
__device__ float4 g_CL2[N_NODES];   // {R3, R5, R4, R6}
__device__ float4 g_CL3a[N_NODES];  // {R7, R10, R11, pad}
__device__ float4 g_CL3b[N_NODES];  // {R8, R9, R12, pad}
__device__ float4 g_CL4[N_NODES];   // {R13, R15, R14, R16}
__device__ float g_D[17][4][64];
__device__ float g_sig[5];
__device__ int g_count;             // barrier arrival counter (returns to 0)
__device__ volatile int g_gen;      // barrier generation (monotonic across replays)

// VEC_ID[s_idx][p_idx] -> vector id for string s++p; order {eps,"0","00","1","11"}
__constant__ int c_VEC_ID[5][5] = {
    {0, 1, 3, 2, 6},
    {1, 3, 7, 4, 9},
    {3, 7, 13, 8, 14},
    {2, 5, 10, 6, 12},
    {6, 11, 15, 12, 16}};
// smem slot s -> original vid
__constant__ int c_SVID[16] = {1, 2, 3, 5, 4, 6, 7, 10, 11, 8, 9, 12, 13, 15, 14, 16};

__device__ __forceinline__ void red2(float* p, float a, float b) {
    asm volatile("red.global.add.v2.f32 [%0], {%1,%2};" :: "l"(p), "f"(a), "f"(b) : "memory");
}
__device__ __forceinline__ void red4(float* p, float a, float b, float c, float d) {
    asm volatile("red.global.add.v4.f32 [%0], {%1,%2,%3,%4};"
                 :: "l"(p), "f"(a), "f"(b), "f"(c), "f"(d) : "memory");
}
// L2-only loads (bypass L1 — required for atomic-written data within one launch)
__device__ __forceinline__ float ldcg1(const float* p) {
    float r; asm volatile("ld.global.cg.f32 %0,[%1];" : "=f"(r) : "l"(p)); return r;
}
__device__ __forceinline__ float2 ldcg2(const float2* p) {
    float2 r; asm volatile("ld.global.cg.v2.f32 {%0,%1},[%2];"
                           : "=f"(r.x), "=f"(r.y) : "l"(p)); return r;
}
__device__ __forceinline__ float4 ldcg4(const float4* p) {
    float4 r; asm volatile("ld.global.cg.v4.f32 {%0,%1,%2,%3},[%4];"
                           : "=f"(r.x), "=f"(r.y), "=f"(r.z), "=f"(r.w) : "l"(p)); return r;
}

__device__ __forceinline__ void gsync() {
    __syncthreads();
    if (threadIdx.x == 0) {
        __threadfence();
        int gen = g_gen;
        if (atomicAdd(&g_count, 1) == NB - 1) {
            g_count = 0;
            __threadfence();
            g_gen = gen + 1;
        } else {
            while (g_gen == gen) __nanosleep(64);
        }
    }
    __syncthreads();
}

__global__ void __launch_bounds__(NT, 1)
fused_kernel(const int* __restrict__ eidx, const float* __restrict__ evals,
             const float* __restrict__ x,
             const float* __restrict__ W1, const float* __restrict__ b1,
             const float* __restrict__ W2, const float* __restrict__ b2,
             float* __restrict__ out) {
    __shared__ float Rs[16 * DCHUNK];    // 8 KB (dot phase)
    __shared__ float4 part[30][32];      // 15 KB (tout partials)
    __shared__ float Ts[5][128];         // 2.5 KB

    const int tid = threadIdx.x;
    const int gtid = blockIdx.x * NT + tid;

    // ---- phase 0: zero ----
    for (int i = gtid; i < N_NODES; i += NTHR) {
        g_CL1[i] = make_float2(0.f, 0.f);
        float4 z = make_float4(0.f, 0.f, 0.f, 0.f);
        g_CL2[i] = z; g_CL3a[i] = z; g_CL3b[i] = z; g_CL4[i] = z;
    }
    for (int i = gtid; i < 17 * 4 * 64; i += NTHR) (&g_D[0][0][0])[i] = 0.f;
    if (gtid < 5) g_sig[gtid] = 0.f;
    gsync();

    // ---- phase 1: lvl1 (parent = e_0, no gather) ----
    for (int q = gtid; q < 2 * QUADS; q += NTHR) {
        int g = q >= QUADS;
        int j = q - g * QUADS;
        const int* eb = eidx + (size_t)g * 2 * N_EDGES;
        int4 r = __ldg((const int4*)eb + j);
        if (r.x == 0 || r.y == 0 || r.z == 0 || r.w == 0) {
            int4 c = __ldg((const int4*)(eb + N_EDGES) + j);
            float4 v = __ldg((const float4*)(evals + (size_t)g * N_EDGES) + j);
            float* base = (float*)g_CL1 + g;
            if (r.x == 0) atomicAdd(base + c.x * 2, v.x);
            if (r.y == 0) atomicAdd(base + c.y * 2, v.y);
            if (r.z == 0) atomicAdd(base + c.z * 2, v.z);
            if (r.w == 0) atomicAdd(base + c.w * 2, v.w);
        }
    }
    gsync();

    // ---- phase 2: lvl2 ----
    for (int q = gtid; q < 2 * QUADS; q += NTHR) {
        int g = q >= QUADS;
        int j = q - g * QUADS;
        const int* eb = eidx + (size_t)g * 2 * N_EDGES;
        int4 r = __ldg((const int4*)eb + j);
        float2 q0 = ldcg2(g_CL1 + r.x), q1 = ldcg2(g_CL1 + r.y);
        float2 q2 = ldcg2(g_CL1 + r.z), q3 = ldcg2(g_CL1 + r.w);
        bool a0 = (q0.x != 0.f) | (q0.y != 0.f);
        bool a1 = (q1.x != 0.f) | (q1.y != 0.f);
        bool a2 = (q2.x != 0.f) | (q2.y != 0.f);
        bool a3 = (q3.x != 0.f) | (q3.y != 0.f);
        if (!(a0 | a1 | a2 | a3)) continue;
        int4 c = __ldg((const int4*)(eb + N_EDGES) + j);
        float4 v = __ldg((const float4*)(evals + (size_t)g * N_EDGES) + j);
        float* base = (float*)g_CL2 + 2 * g;
        if (a0) red2(base + c.x * 4, v.x * q0.x, v.x * q0.y);
        if (a1) red2(base + c.y * 4, v.y * q1.x, v.y * q1.y);
        if (a2) red2(base + c.z * 4, v.z * q2.x, v.z * q2.y);
        if (a3) red2(base + c.w * 4, v.w * q3.x, v.w * q3.y);
    }
    gsync();

    // ---- phase 3: lvl3 ----
    for (int q = gtid; q < 2 * QUADS; q += NTHR) {
        int g = q >= QUADS;
        int j = q - g * QUADS;
        const int* eb = eidx + (size_t)g * 2 * N_EDGES;
        int4 r = __ldg((const int4*)eb + j);
        float4 qq[4] = {ldcg4(g_CL2 + r.x), ldcg4(g_CL2 + r.y),
                        ldcg4(g_CL2 + r.z), ldcg4(g_CL2 + r.w)};
        float p[4][3];
        bool any[4];
#pragma unroll
        for (int i = 0; i < 4; i++) {
            p[i][0] = qq[i].x;
            p[i][1] = g ? qq[i].z : qq[i].y;
            p[i][2] = qq[i].w;
            any[i] = (p[i][0] != 0.f) | (p[i][1] != 0.f) | (p[i][2] != 0.f);
        }
        if (!(any[0] | any[1] | any[2] | any[3])) continue;
        int4 c = __ldg((const int4*)(eb + N_EDGES) + j);
        float4 v = __ldg((const float4*)(evals + (size_t)g * N_EDGES) + j);
        float4* dst = g ? g_CL3b : g_CL3a;
        const int ci[4] = {c.x, c.y, c.z, c.w};
        const float vv[4] = {v.x, v.y, v.z, v.w};
#pragma unroll
        for (int i = 0; i < 4; i++)
            if (any[i])
                red4((float*)&dst[ci[i]], vv[i] * p[i][0], vv[i] * p[i][1], vv[i] * p[i][2], 0.f);
    }
    gsync();

    // ---- phase 4: lvl4 ----
    for (int q = gtid; q < 2 * QUADS; q += NTHR) {
        int g = q >= QUADS;
        int j = q - g * QUADS;
        const int* eb = eidx + (size_t)g * 2 * N_EDGES;
        const float4* src = g ? g_CL3b : g_CL3a;
        int4 r = __ldg((const int4*)eb + j);
        float4 q0 = ldcg4(src + r.x), q1 = ldcg4(src + r.y);
        float4 q2 = ldcg4(src + r.z), q3 = ldcg4(src + r.w);
        int4 c = __ldg((const int4*)(eb + N_EDGES) + j);
        float4 v = __ldg((const float4*)(evals + (size_t)g * N_EDGES) + j);
        float* base = (float*)g_CL4 + 2 * g;
        if ((q0.x != 0.f) | (q0.z != 0.f)) red2(base + c.x * 4, v.x * q0.x, v.x * q0.z);
        if ((q1.x != 0.f) | (q1.z != 0.f)) red2(base + c.y * 4, v.y * q1.x, v.y * q1.z);
        if ((q2.x != 0.f) | (q2.z != 0.f)) red2(base + c.z * 4, v.z * q2.x, v.z * q2.z);
        if ((q3.x != 0.f) | (q3.z != 0.f)) red2(base + c.w * 4, v.w * q3.x, v.w * q3.z);
    }
    gsync();

    // ---- phase 5: dot  D[v][b][f] = sum_n R[v][n] x[b][n][f]; sigma folded ----
    {
        int f = tid & 63;
        int bb = (tid >> 6) & 3;
        int vg = tid >> 8;  // 0..3 -> slots vg*4..vg*4+3
        for (int c = blockIdx.x; c < NCHUNK; c += NB) {
            int n0 = c * DCHUNK;
            if (tid < 5 * 128) {
                int n = tid & 127, grp = tid >> 7;
                int gn = n0 + n;
                bool ok = gn < N_NODES;
                float4 z = make_float4(0.f, 0.f, 0.f, 0.f);
                if (grp == 0) {
                    float2 a = ok ? ldcg2(g_CL1 + gn) : make_float2(0.f, 0.f);
                    Rs[0 * DCHUNK + n] = a.x; Rs[1 * DCHUNK + n] = a.y;
                } else if (grp == 1) {
                    float4 a = ok ? ldcg4(g_CL2 + gn) : z;
                    Rs[2 * DCHUNK + n] = a.x; Rs[3 * DCHUNK + n] = a.y;
                    Rs[4 * DCHUNK + n] = a.z; Rs[5 * DCHUNK + n] = a.w;
                } else if (grp == 2) {
                    float4 a = ok ? ldcg4(g_CL3a + gn) : z;
                    Rs[6 * DCHUNK + n] = a.x; Rs[7 * DCHUNK + n] = a.y;
                    Rs[8 * DCHUNK + n] = a.z;
                } else if (grp == 3) {
                    float4 a = ok ? ldcg4(g_CL3b + gn) : z;
                    Rs[9 * DCHUNK + n] = a.x; Rs[10 * DCHUNK + n] = a.y;
                    Rs[11 * DCHUNK + n] = a.z;
                } else {
                    float4 a = ok ? ldcg4(g_CL4 + gn) : z;
                    Rs[12 * DCHUNK + n] = a.x; Rs[13 * DCHUNK + n] = a.y;
                    Rs[14 * DCHUNK + n] = a.z; Rs[15 * DCHUNK + n] = a.w;
                }
            }
            __syncthreads();
            if (tid < 128) {  // sigma: vids {1,3,2,6} = slots {0,2,1,5}
                const int slots[4] = {0, 2, 1, 5};
                int vi = tid >> 5, lane = tid & 31;
                float s = 0.f;
                for (int n = lane; n < DCHUNK; n += 32) s += Rs[slots[vi] * DCHUNK + n];
#pragma unroll
                for (int off = 16; off; off >>= 1) s += __shfl_down_sync(0xffffffffu, s, off);
                if (lane == 0) atomicAdd(&g_sig[vi + 1], s);
            }
            float acc0 = 0.f, acc1 = 0.f, acc2 = 0.f, acc3 = 0.f;
            const float* xb = x + ((size_t)bb * N_NODES + n0) * 64 + f;
            const float* rsv = Rs + vg * 4 * DCHUNK;
            int lim = min(DCHUNK, N_NODES - n0);
            for (int nn = 0; nn < lim; nn++) {
                float xv = __ldg(xb + (size_t)nn * 64);
                acc0 += rsv[0 * DCHUNK + nn] * xv;
                acc1 += rsv[1 * DCHUNK + nn] * xv;
                acc2 += rsv[2 * DCHUNK + nn] * xv;
                acc3 += rsv[3 * DCHUNK + nn] * xv;
            }
            atomicAdd(&g_D[c_SVID[vg * 4 + 0]][bb][f], acc0);
            atomicAdd(&g_D[c_SVID[vg * 4 + 1]][bb][f], acc1);
            atomicAdd(&g_D[c_SVID[vg * 4 + 2]][bb][f], acc2);
            atomicAdd(&g_D[c_SVID[vg * 4 + 3]][bb][f], acc3);
            __syncthreads();
        }
    }
    gsync();

    // ---- phase 6: tout (blocks 0..3, one per batch) ----
    if (blockIdx.x < 4) {
        int b = blockIdx.x;
        int lane = tid & 31, w = tid >> 5;  // 32 warps
        if (w < 30) {  // (si, pc) pairs, layer 1
            int si = w / 6, pc = w % 6;
            int e = pc / 3, k = pc % 3;
            int pi = (k == 0) ? 0 : (e * 2 + k);
            int vid = c_VEC_ID[si][pi];
            const float* Dp = vid ? g_D[vid][b] : (x + (size_t)b * N_NODES * 64);
            const float* Wp = W1 + (size_t)pc * 64 * 128;
            float4 acc = {0.f, 0.f, 0.f, 0.f};
            for (int f = 0; f < 64; f++) {
                float d = ldcg1(Dp + f);
                float4 wv = __ldg((const float4*)(Wp + (size_t)f * 128) + lane);
                acc.x += d * wv.x; acc.y += d * wv.y; acc.z += d * wv.z; acc.w += d * wv.w;
            }
            part[w][lane] = acc;
        }
        __syncthreads();
        if (w < 5) {
            float sg = (w == 0) ? 1.0f : ldcg1(&g_sig[w]);
            float4 bb = __ldg((const float4*)b1 + lane);
            float4 o = {sg * bb.x, sg * bb.y, sg * bb.z, sg * bb.w};
#pragma unroll
            for (int p = 0; p < 6; p++) {
                float4 a = part[w * 6 + p][lane];
                o.x += a.x; o.y += a.y; o.z += a.z; o.w += a.w;
            }
            ((float4*)Ts[w])[lane] = o;
        }
        __syncthreads();
        if (w < 6) {  // layer 2 per (e',k')
            int e = w / 3, k = w % 3;
            int si = (k == 0) ? 0 : (e * 2 + k);
            const float* Tp = Ts[si];
            const float* Wp = W2 + (size_t)w * 128 * 128;
            float4 acc = {0.f, 0.f, 0.f, 0.f};
            for (int f = 0; f < 128; f++) {
                float t = Tp[f];
                float4 wv = __ldg((const float4*)(Wp + (size_t)f * 128) + lane);
                acc.x += t * wv.x; acc.y += t * wv.y; acc.z += t * wv.z; acc.w += t * wv.w;
            }
            part[w][lane] = acc;
        }
        __syncthreads();
        if (w == 0) {
            float4 o = __ldg((const float4*)b2 + lane);
#pragma unroll
            for (int p = 0; p < 6; p++) {
                float4 a = part[p][lane];
                o.x += a.x; o.y += a.y; o.z += a.z; o.w += a.w;
            }
            ((float4*)(out + (size_t)b * 128))[lane] = o;
        }
    }
}

extern "C" void kernel_launch(void* const* d_in, const int* in_sizes, int n_in,
                              void* d_out, int out_size) {
    const float* x = nullptr;
    const int* eidx = nullptr;
    const float* evals = nullptr;
    const float *W1 = nullptr, *b1 = nullptr, *W2 = nullptr, *b2 = nullptr;
    for (int i = 0; i < n_in; i++) {
        switch (in_sizes[i]) {
            case 2560000: x = (const float*)d_in[i]; break;
            case 1280000: eidx = (const int*)d_in[i]; break;
            case 640000:  evals = (const float*)d_in[i]; break;
            case 49152:   W1 = (const float*)d_in[i]; break;
            case 98304:   W2 = (const float*)d_in[i]; break;
            case 128:
                if (!b1) b1 = (const float*)d_in[i];
                else b2 = (const float*)d_in[i];
                break;
        }
    }
    float* out = (float*)d_out;
    fused_kernel<<<NB, NT>>>(eidx, evals, x, W1, b1, W2, b2, out);
}

// round 5
// speedup vs baseline: 1.6258x; 1.2535x over previous
#include <cuda_runtime.h>

#define N_NODES 10000
#define N_EDGES 320000
#define QUADS (N_EDGES / 4)
#define NB 148
#define NT 1024
#define NTHR (NB * NT)
#define DCHUNK 72
#define NCHUNK ((N_NODES + DCHUNK - 1) / DCHUNK)  // 139
#define BM_WORDS 320

// Packed probe-vector storage (struct-of-slots per tree level).
__device__ float2 g_CL1[N_NODES];   // {R1, R2}
__device__ float4 g_CL2[N_NODES];   // {R3, R5, R4, R6}
__device__ float4 g_CL3a[N_NODES];  // {R7, R10, R11, pad}
__device__ float4 g_CL3b[N_NODES];  // {R8, R9, R12, pad}
__device__ float4 g_CL4[N_NODES];   // {R13, R15, R14, R16}
__device__ unsigned g_bm1[BM_WORDS];  // supp(CL1) bitmap (over-approx, safe)
__device__ unsigned g_bm2[BM_WORDS];  // supp(CL2) bitmap
__device__ float g_D[17][4][64];
__device__ float g_T[5][4][128];
__device__ float g_sig[5];
__device__ int g_count;
__device__ volatile int g_gen;

// VEC_ID[s_idx][p_idx] -> vector id for string s++p; order {eps,"0","00","1","11"}
__constant__ int c_VEC_ID[5][5] = {
    {0, 1, 3, 2, 6},
    {1, 3, 7, 4, 9},
    {3, 7, 13, 8, 14},
    {2, 5, 10, 6, 12},
    {6, 11, 15, 12, 16}};
// Rs smem slot s -> original vid
__constant__ int c_SVID[16] = {1, 2, 3, 5, 4, 6, 7, 10, 11, 8, 9, 12, 13, 15, 14, 16};

__device__ __forceinline__ void red2(float* p, float a, float b) {
    asm volatile("red.global.add.v2.f32 [%0], {%1,%2};" :: "l"(p), "f"(a), "f"(b) : "memory");
}
__device__ __forceinline__ void red4(float* p, float a, float b, float c, float d) {
    asm volatile("red.global.add.v4.f32 [%0], {%1,%2,%3,%4};"
                 :: "l"(p), "f"(a), "f"(b), "f"(c), "f"(d) : "memory");
}
// L2-only loads for data written by atomics/reds within this launch.
__device__ __forceinline__ float ldcg1(const float* p) {
    float r; asm volatile("ld.global.cg.f32 %0,[%1];" : "=f"(r) : "l"(p)); return r;
}
__device__ __forceinline__ unsigned ldcg1u(const unsigned* p) {
    unsigned r; asm volatile("ld.global.cg.u32 %0,[%1];" : "=r"(r) : "l"(p)); return r;
}
__device__ __forceinline__ float2 ldcg2(const float2* p) {
    float2 r; asm volatile("ld.global.cg.v2.f32 {%0,%1},[%2];"
                           : "=f"(r.x), "=f"(r.y) : "l"(p)); return r;
}
__device__ __forceinline__ float4 ldcg4(const float4* p) {
    float4 r; asm volatile("ld.global.cg.v4.f32 {%0,%1,%2,%3},[%4];"
                           : "=f"(r.x), "=f"(r.y), "=f"(r.z), "=f"(r.w) : "l"(p)); return r;
}

__device__ __forceinline__ void barrier_arrive(int target) {
    __syncthreads();
    if (threadIdx.x == 0) {
        __threadfence();
        int gen = g_gen;
        if (atomicAdd(&g_count, 1) == target - 1) {
            g_count = 0;
            __threadfence();
            g_gen = gen + 1;
        }
    }
}
__device__ __forceinline__ void barrier_wait(int target) {
    __syncthreads();
    if (threadIdx.x == 0) {
        __threadfence();
        int gen = g_gen;
        if (atomicAdd(&g_count, 1) == target - 1) {
            g_count = 0;
            __threadfence();
            g_gen = gen + 1;
        } else {
            while (g_gen == gen) __nanosleep(64);
        }
    }
    __syncthreads();
}

__global__ void __launch_bounds__(NT, 1)
fused_kernel(const int* __restrict__ eidx, const float* __restrict__ evals,
             const float* __restrict__ x,
             const float* __restrict__ W1, const float* __restrict__ b1,
             const float* __restrict__ W2, const float* __restrict__ b2,
             float* __restrict__ out) {
    __shared__ float Rs[16 * DCHUNK];     // 4.6 KB
    __shared__ unsigned sbm[BM_WORDS];    // 1.25 KB
    __shared__ float4 part[12][32];       // 6 KB

    const int tid = threadIdx.x;
    const int gtid = blockIdx.x * NT + tid;
    const float4 z4 = make_float4(0.f, 0.f, 0.f, 0.f);

    // ---- P0: zero CL1, bitmaps, D, T, sig ----
    for (int i = gtid; i < N_NODES; i += NTHR) g_CL1[i] = make_float2(0.f, 0.f);
    for (int i = gtid; i < 17 * 4 * 64; i += NTHR) (&g_D[0][0][0])[i] = 0.f;
    for (int i = gtid; i < 5 * 4 * 128; i += NTHR) (&g_T[0][0][0])[i] = 0.f;
    if (gtid < BM_WORDS) { g_bm1[gtid] = 0u; g_bm2[gtid] = 0u; }
    if (gtid < 5) g_sig[gtid] = 0.f;
    barrier_wait(NB);

    // ---- P1: lvl1 (parent = e_0, no gather) + build bm1 + zero CL2 ----
    for (int i = gtid; i < N_NODES; i += NTHR) g_CL2[i] = z4;
    for (int q = gtid; q < 2 * QUADS; q += NTHR) {
        int g = q >= QUADS;
        int j = q - g * QUADS;
        const int* eb = eidx + (size_t)g * 2 * N_EDGES;
        int4 r = __ldg((const int4*)eb + j);
        if (r.x == 0 || r.y == 0 || r.z == 0 || r.w == 0) {
            int4 c = __ldg((const int4*)(eb + N_EDGES) + j);
            float4 v = __ldg((const float4*)(evals + (size_t)g * N_EDGES) + j);
            float* base = (float*)g_CL1 + g;
            const int ri[4] = {r.x, r.y, r.z, r.w};
            const int ci[4] = {c.x, c.y, c.z, c.w};
            const float vv[4] = {v.x, v.y, v.z, v.w};
#pragma unroll
            for (int i = 0; i < 4; i++)
                if (ri[i] == 0) {
                    atomicAdd(base + ci[i] * 2, vv[i]);
                    atomicOr(&g_bm1[ci[i] >> 5], 1u << (ci[i] & 31));
                }
        }
    }
    barrier_wait(NB);

    // ---- P2: lvl2 (bm1-filtered) + build bm2 + zero CL3 ----
    if (tid < BM_WORDS) sbm[tid] = ldcg1u(&g_bm1[tid]);
    __syncthreads();
    for (int i = gtid; i < N_NODES; i += NTHR) { g_CL3a[i] = z4; g_CL3b[i] = z4; }
    for (int q = gtid; q < 2 * QUADS; q += NTHR) {
        int g = q >= QUADS;
        int j = q - g * QUADS;
        const int* eb = eidx + (size_t)g * 2 * N_EDGES;
        int4 r = __ldg((const int4*)eb + j);
        const int ri[4] = {r.x, r.y, r.z, r.w};
        unsigned m[4];
        unsigned any = 0;
#pragma unroll
        for (int i = 0; i < 4; i++) {
            m[i] = (sbm[ri[i] >> 5] >> (ri[i] & 31)) & 1u;
            any |= m[i];
        }
        if (!any) continue;
        int4 c = __ldg((const int4*)(eb + N_EDGES) + j);
        float4 v = __ldg((const float4*)(evals + (size_t)g * N_EDGES) + j);
        const int ci[4] = {c.x, c.y, c.z, c.w};
        const float vv[4] = {v.x, v.y, v.z, v.w};
        float* base = (float*)g_CL2 + 2 * g;
#pragma unroll
        for (int i = 0; i < 4; i++)
            if (m[i]) {
                float2 qv = ldcg2(g_CL1 + ri[i]);
                if ((qv.x != 0.f) | (qv.y != 0.f)) {
                    red2(base + ci[i] * 4, vv[i] * qv.x, vv[i] * qv.y);
                    atomicOr(&g_bm2[ci[i] >> 5], 1u << (ci[i] & 31));
                }
            }
    }
    barrier_wait(NB);

    // ---- P3: lvl3 (bm2-filtered) + zero CL4 ----
    if (tid < BM_WORDS) sbm[tid] = ldcg1u(&g_bm2[tid]);
    __syncthreads();
    for (int i = gtid; i < N_NODES; i += NTHR) g_CL4[i] = z4;
    for (int q = gtid; q < 2 * QUADS; q += NTHR) {
        int g = q >= QUADS;
        int j = q - g * QUADS;
        const int* eb = eidx + (size_t)g * 2 * N_EDGES;
        int4 r = __ldg((const int4*)eb + j);
        const int ri[4] = {r.x, r.y, r.z, r.w};
        unsigned m[4];
        unsigned any = 0;
#pragma unroll
        for (int i = 0; i < 4; i++) {
            m[i] = (sbm[ri[i] >> 5] >> (ri[i] & 31)) & 1u;
            any |= m[i];
        }
        if (!any) continue;
        int4 c = __ldg((const int4*)(eb + N_EDGES) + j);
        float4 v = __ldg((const float4*)(evals + (size_t)g * N_EDGES) + j);
        float4* dst = g ? g_CL3b : g_CL3a;
        const int ci[4] = {c.x, c.y, c.z, c.w};
        const float vv[4] = {v.x, v.y, v.z, v.w};
#pragma unroll
        for (int i = 0; i < 4; i++)
            if (m[i]) {
                float4 qv = ldcg4(g_CL2 + ri[i]);
                float p0 = qv.x;
                float p1 = g ? qv.z : qv.y;
                float p2 = qv.w;
                if ((p0 != 0.f) | (p1 != 0.f) | (p2 != 0.f))
                    red4((float*)&dst[ci[i]], vv[i] * p0, vv[i] * p1, vv[i] * p2, 0.f);
            }
    }
    barrier_wait(NB);

    // ---- P4: lvl4 (dense) ----
    for (int q = gtid; q < 2 * QUADS; q += NTHR) {
        int g = q >= QUADS;
        int j = q - g * QUADS;
        const int* eb = eidx + (size_t)g * 2 * N_EDGES;
        const float4* src = g ? g_CL3b : g_CL3a;
        int4 r = __ldg((const int4*)eb + j);
        float4 q0 = ldcg4(src + r.x), q1 = ldcg4(src + r.y);
        float4 q2 = ldcg4(src + r.z), q3 = ldcg4(src + r.w);
        int4 c = __ldg((const int4*)(eb + N_EDGES) + j);
        float4 v = __ldg((const float4*)(evals + (size_t)g * N_EDGES) + j);
        float* base = (float*)g_CL4 + 2 * g;
        if ((q0.x != 0.f) | (q0.z != 0.f)) red2(base + c.x * 4, v.x * q0.x, v.x * q0.z);
        if ((q1.x != 0.f) | (q1.z != 0.f)) red2(base + c.y * 4, v.y * q1.x, v.y * q1.z);
        if ((q2.x != 0.f) | (q2.z != 0.f)) red2(base + c.z * 4, v.z * q2.x, v.z * q2.z);
        if ((q3.x != 0.f) | (q3.z != 0.f)) red2(base + c.w * 4, v.w * q3.x, v.w * q3.z);
    }
    barrier_wait(NB);

    // ---- P5: dot  D[v][b][f] = sum_n R[v][n] x[b][n][f]; sigma folded ----
    if (blockIdx.x < NCHUNK) {
        int n0 = blockIdx.x * DCHUNK;
        int lim = min(DCHUNK, N_NODES - n0);
        if (tid < DCHUNK) {
            int gn = n0 + tid;
            bool ok = gn < N_NODES;
            float2 a = ok ? ldcg2(g_CL1 + gn) : make_float2(0.f, 0.f);
            float4 c2 = ok ? ldcg4(g_CL2 + gn) : z4;
            float4 c3a = ok ? ldcg4(g_CL3a + gn) : z4;
            float4 c3b = ok ? ldcg4(g_CL3b + gn) : z4;
            float4 c4 = ok ? ldcg4(g_CL4 + gn) : z4;
            Rs[0 * DCHUNK + tid] = a.x;   Rs[1 * DCHUNK + tid] = a.y;
            Rs[2 * DCHUNK + tid] = c2.x;  Rs[3 * DCHUNK + tid] = c2.y;
            Rs[4 * DCHUNK + tid] = c2.z;  Rs[5 * DCHUNK + tid] = c2.w;
            Rs[6 * DCHUNK + tid] = c3a.x; Rs[7 * DCHUNK + tid] = c3a.y;
            Rs[8 * DCHUNK + tid] = c3a.z;
            Rs[9 * DCHUNK + tid] = c3b.x; Rs[10 * DCHUNK + tid] = c3b.y;
            Rs[11 * DCHUNK + tid] = c3b.z;
            Rs[12 * DCHUNK + tid] = c4.x; Rs[13 * DCHUNK + tid] = c4.y;
            Rs[14 * DCHUNK + tid] = c4.z; Rs[15 * DCHUNK + tid] = c4.w;
        }
        __syncthreads();
        if (tid < 128) {  // sigma: vids {1,3,2,6} = slots {0,2,1,5}
            const int slots[4] = {0, 2, 1, 5};
            int vi = tid >> 5, lane = tid & 31;
            float s = 0.f;
            for (int n = lane; n < DCHUNK; n += 32) s += Rs[slots[vi] * DCHUNK + n];
#pragma unroll
            for (int off = 16; off; off >>= 1) s += __shfl_down_sync(0xffffffffu, s, off);
            if (lane == 0) atomicAdd(&g_sig[vi + 1], s);
        }
        int f = tid & 63;
        int bb = (tid >> 6) & 3;
        int vg = tid >> 8;
        float acc0 = 0.f, acc1 = 0.f, acc2 = 0.f, acc3 = 0.f;
        const float* xb = x + ((size_t)bb * N_NODES + n0) * 64 + f;
        const float* rsv = Rs + vg * 4 * DCHUNK;
        for (int nn = 0; nn < lim; nn++) {
            float xv = __ldg(xb + (size_t)nn * 64);
            acc0 += rsv[0 * DCHUNK + nn] * xv;
            acc1 += rsv[1 * DCHUNK + nn] * xv;
            acc2 += rsv[2 * DCHUNK + nn] * xv;
            acc3 += rsv[3 * DCHUNK + nn] * xv;
        }
        atomicAdd(&g_D[c_SVID[vg * 4 + 0]][bb][f], acc0);
        atomicAdd(&g_D[c_SVID[vg * 4 + 1]][bb][f], acc1);
        atomicAdd(&g_D[c_SVID[vg * 4 + 2]][bb][f], acc2);
        atomicAdd(&g_D[c_SVID[vg * 4 + 3]][bb][f], acc3);
    }
    if (blockIdx.x >= 124) { barrier_arrive(NB); return; }
    barrier_wait(NB);

    // ---- P6a: T partials (blocks 0..119: (b,si,pc)); blocks 120..123 init out=b2 ----
    {
        int id = blockIdx.x;
        int lane = tid & 31, w = tid >> 5;
        if (id < 120) {
            int b = id & 3, si = (id >> 2) % 5, pc = id / 20;
            int e = pc / 3, k = pc % 3;
            int pi = (k == 0) ? 0 : (e * 2 + k);
            int vid = c_VEC_ID[si][pi];
            const float* Dp = vid ? &g_D[vid][b][0] : (x + (size_t)b * N_NODES * 64);
            const float* Wp = W1 + (size_t)pc * 64 * 128;
            if (w < 12) {
                float4 acc = z4;
                for (int f = w; f < 64; f += 12) {
                    float d = vid ? ldcg1(Dp + f) : __ldg(Dp + f);
                    float4 wv = __ldg((const float4*)(Wp + (size_t)f * 128) + lane);
                    acc.x += d * wv.x; acc.y += d * wv.y;
                    acc.z += d * wv.z; acc.w += d * wv.w;
                }
                part[w][lane] = acc;
            }
            __syncthreads();
            if (w == 0) {
                float4 o = z4;
#pragma unroll
                for (int i = 0; i < 12; i++) {
                    float4 a = part[i][lane];
                    o.x += a.x; o.y += a.y; o.z += a.z; o.w += a.w;
                }
                float* tp = &g_T[si][b][lane * 4];
                atomicAdd(tp + 0, o.x); atomicAdd(tp + 1, o.y);
                atomicAdd(tp + 2, o.z); atomicAdd(tp + 3, o.w);
            }
        } else {
            // blocks 120..123: out[b] = b2
            int b = id - 120;
            if (tid < 32)
                ((float4*)(out + (size_t)b * 128))[tid] = __ldg((const float4*)b2 + tid);
        }
    }
    if (blockIdx.x >= 24) { barrier_arrive(124); return; }
    barrier_wait(124);

    // ---- P6b: out partials (blocks 0..23: (b,pc)) ----
    {
        int id = blockIdx.x;
        int b = id & 3, pc = id >> 2;
        int e = pc / 3, k = pc % 3;
        int si = (k == 0) ? 0 : (e * 2 + k);
        float sg = (si == 0) ? 1.0f : ldcg1(&g_sig[si]);
        int lane = tid & 31, w = tid >> 5;
        const float* Tp = &g_T[si][b][0];
        const float* Wp = W2 + (size_t)pc * 128 * 128;
        if (w < 12) {
            float4 acc = z4;
            for (int f = w; f < 128; f += 12) {
                float t = ldcg1(Tp + f) + sg * __ldg(b1 + f);
                float4 wv = __ldg((const float4*)(Wp + (size_t)f * 128) + lane);
                acc.x += t * wv.x; acc.y += t * wv.y;
                acc.z += t * wv.z; acc.w += t * wv.w;
            }
            part[w][lane] = acc;
        }
        __syncthreads();
        if (w == 0) {
            float4 o = z4;
#pragma unroll
            for (int i = 0; i < 12; i++) {
                float4 a = part[i][lane];
                o.x += a.x; o.y += a.y; o.z += a.z; o.w += a.w;
            }
            float* op = out + (size_t)b * 128 + lane * 4;
            atomicAdd(op + 0, o.x); atomicAdd(op + 1, o.y);
            atomicAdd(op + 2, o.z); atomicAdd(op + 3, o.w);
        }
    }
}

extern "C" void kernel_launch(void* const* d_in, const int* in_sizes, int n_in,
                              void* d_out, int out_size) {
    const float* x = nullptr;
    const int* eidx = nullptr;
    const float* evals = nullptr;
    const float *W1 = nullptr, *b1 = nullptr, *W2 = nullptr, *b2 = nullptr;
    for (int i = 0; i < n_in; i++) {
        switch (in_sizes[i]) {
            case 2560000: x = (const float*)d_in[i]; break;
            case 1280000: eidx = (const int*)d_in[i]; break;
            case 640000:  evals = (const float*)d_in[i]; break;
            case 49152:   W1 = (const float*)d_in[i]; break;
            case 98304:   W2 = (const float*)d_in[i]; break;
            case 128:
                if (!b1) b1 = (const float*)d_in[i];
                else b2 = (const float*)d_in[i];
                break;
        }
    }
    float* out = (float*)d_out;
    fused_kernel<<<NB, NT>>>(eidx, evals, x, W1, b1, W2, b2, out);
}